// round 8
// baseline (speedup 1.0000x reference)
#include <cuda_runtime.h>
#include <cstdint>

#define BATCH 2
#define SEQ   2048
#define DMODEL 768
#define NHEAD 12
#define HDIM  64
#define MROWS (BATCH*SEQ)      // 4096
#define QTILES (SEQ/128)       // 16
#define NTILES (QTILES*BATCH*NHEAD)  // 384
#define ATTN_GRID 296          // 2 CTAs x 148 SMs

// Scratch Q/K/V in [B,H,S,hd], stored as tf32 bit patterns (Q pre-scaled 1/8)
__device__ unsigned int g_q[BATCH*NHEAD*SEQ*HDIM];
__device__ unsigned int g_k[BATCH*NHEAD*SEQ*HDIM];
__device__ unsigned int g_v[BATCH*NHEAD*SEQ*HDIM];
__device__ unsigned int g_ctr;   // dynamic tile counter for attn

// ---------------------------------------------------------------------------
// helpers
// ---------------------------------------------------------------------------
__device__ __forceinline__ uint32_t f2tf(float x) {
    uint32_t u;
    asm("cvt.rna.tf32.f32 %0, %1;" : "=r"(u) : "f"(x));
    return u;
}
__device__ __forceinline__ void split_tf(float x, uint32_t& h, uint32_t& l) {
    h = f2tf(x);
    l = f2tf(x - __uint_as_float(h));
}
// permutation within each 8-group: (t, t+4) -> (2t, 2t+1) adjacent
__device__ __forceinline__ int P8(int c) {
    return (c & ~7) | ((c & 3) << 1) | ((c & 7) >> 2);
}
// permutation within each 16-group: (g, g+8) -> (2g, 2g+1) adjacent
__device__ __forceinline__ int P16(int m) {
    return (m & ~15) | ((m & 7) << 1) | ((m & 15) >> 3);
}
__device__ __forceinline__ void mma8(float* c,
    uint32_t a0, uint32_t a1, uint32_t a2, uint32_t a3,
    uint32_t b0, uint32_t b1)
{
    asm volatile(
        "mma.sync.aligned.m16n8k8.row.col.f32.tf32.tf32.f32 "
        "{%0,%1,%2,%3}, {%4,%5,%6,%7}, {%8,%9}, {%0,%1,%2,%3};"
        : "+f"(c[0]), "+f"(c[1]), "+f"(c[2]), "+f"(c[3])
        : "r"(a0), "r"(a1), "r"(a2), "r"(a3), "r"(b0), "r"(b1));
}

// ---------------------------------------------------------------------------
// Kernel 1: QKV projection, 3xTF32, LDS.64 fragment layouts.
// 256 thr (8 warps: wy 0..3, wx 0..1), BM=128, BN=64, BK=16, warp m32xn32.
// A smem [k][perm16(m)] stride 136; B smem [n][P8(k)] stride 24.
// Outputs written as tf32 bits to [B,H,S,hd] (Q pre-scaled 1/8).
// ---------------------------------------------------------------------------
__global__ __launch_bounds__(256, 2) void qkv_kernel(
    const float* __restrict__ X,
    const float* __restrict__ Wq, const float* __restrict__ bq,
    const float* __restrict__ Wk, const float* __restrict__ bk,
    const float* __restrict__ Wv, const float* __restrict__ bv)
{
    if (blockIdx.x == 0 && blockIdx.y == 0 && blockIdx.z == 0 && threadIdx.x == 0)
        g_ctr = ATTN_GRID;

    const int z = blockIdx.z;
    const float* __restrict__ W    = (z == 0) ? Wq : (z == 1) ? Wk : Wv;
    const float* __restrict__ bias = (z == 0) ? bq : (z == 1) ? bk : bv;
    unsigned int* __restrict__ out = (z == 0) ? g_q : (z == 1) ? g_k : g_v;
    const float osc = (z == 0) ? 0.125f : 1.0f;

    __shared__ uint32_t Ah[16][136], Al[16][136];   // [k][perm16(m)]
    __shared__ uint32_t Bh[64][24],  Bl[64][24];    // [n][P8(k)]

    const int tid  = threadIdx.x;
    const int warp = tid >> 5;
    const int lane = tid & 31;
    const int g = lane >> 2;
    const int t = lane & 3;
    const int wy = warp >> 1;
    const int wx = warp & 1;

    const int m0 = blockIdx.y * 128;
    const int n0 = blockIdx.x * 64;

    // A mapping: idx = tid + e*256; c4 = idx>>7 (k-chunk), r = idx&127 (m)
    // B mapping: idx = tid; rB = idx&15 (k), cB4 = idx>>4 (n-chunk)
    const int rB  = tid & 15;
    const int cB4 = tid >> 4;

    float acc[2][4][4] = {};
    float4 pa[2], pb;

    // prefetch first tile
    #pragma unroll
    for (int e = 0; e < 2; e++) {
        int idx = tid + e * 256;
        pa[e] = *reinterpret_cast<const float4*>(
            X + (m0 + (idx & 127)) * DMODEL + 4 * (idx >> 7));
    }
    pb = *reinterpret_cast<const float4*>(W + rB * DMODEL + n0 + 4 * cB4);

    for (int k0 = 0; k0 < DMODEL; k0 += 16) {
        __syncthreads();   // previous MMA loop done reading smem
        // store A splits
        #pragma unroll
        for (int e = 0; e < 2; e++) {
            int idx = tid + e * 256;
            int c4 = idx >> 7, col = P16(idx & 127);
            const float* v = reinterpret_cast<const float*>(&pa[e]);
            #pragma unroll
            for (int j = 0; j < 4; j++) {
                uint32_t h, l; split_tf(v[j], h, l);
                Ah[4 * c4 + j][col] = h;
                Al[4 * c4 + j][col] = l;
            }
        }
        // store B splits
        {
            int col = P8(rB);
            const float* v = reinterpret_cast<const float*>(&pb);
            #pragma unroll
            for (int j = 0; j < 4; j++) {
                uint32_t h, l; split_tf(v[j], h, l);
                Bh[4 * cB4 + j][col] = h;
                Bl[4 * cB4 + j][col] = l;
            }
        }
        __syncthreads();

        // prefetch next tile (overlaps MMA loop)
        if (k0 + 16 < DMODEL) {
            #pragma unroll
            for (int e = 0; e < 2; e++) {
                int idx = tid + e * 256;
                pa[e] = *reinterpret_cast<const float4*>(
                    X + (m0 + (idx & 127)) * DMODEL + k0 + 16 + 4 * (idx >> 7));
            }
            pb = *reinterpret_cast<const float4*>(
                W + (k0 + 16 + rB) * DMODEL + n0 + 4 * cB4);
        }

        #pragma unroll
        for (int kk = 0; kk < 16; kk += 8) {
            uint2 ah01[2], ah23[2], al01[2], al23[2];
            #pragma unroll
            for (int mt = 0; mt < 2; mt++) {
                int cb = wy * 32 + mt * 16 + 2 * g;
                ah01[mt] = *reinterpret_cast<const uint2*>(&Ah[kk + t][cb]);
                ah23[mt] = *reinterpret_cast<const uint2*>(&Ah[kk + t + 4][cb]);
                al01[mt] = *reinterpret_cast<const uint2*>(&Al[kk + t][cb]);
                al23[mt] = *reinterpret_cast<const uint2*>(&Al[kk + t + 4][cb]);
            }
            #pragma unroll
            for (int nt = 0; nt < 4; nt++) {
                int nr = wx * 32 + nt * 8 + g;
                uint2 bh = *reinterpret_cast<const uint2*>(&Bh[nr][kk + 2 * t]);
                uint2 bl = *reinterpret_cast<const uint2*>(&Bl[nr][kk + 2 * t]);
                #pragma unroll
                for (int mt = 0; mt < 2; mt++) {
                    mma8(acc[mt][nt], ah01[mt].x, ah01[mt].y, ah23[mt].x, ah23[mt].y, bh.x, bh.y);
                    mma8(acc[mt][nt], ah01[mt].x, ah01[mt].y, ah23[mt].x, ah23[mt].y, bl.x, bl.y);
                    mma8(acc[mt][nt], al01[mt].x, al01[mt].y, al23[mt].x, al23[mt].y, bh.x, bh.y);
                }
            }
        }
    }

    // Epilogue: +bias, scale, convert to tf32 bits, scatter to [B,H,S,hd]
    const int h = n0 >> 6;
    #pragma unroll
    for (int mt = 0; mt < 2; mt++) {
        #pragma unroll
        for (int hs = 0; hs < 2; hs++) {
            int mg = m0 + wy * 32 + mt * 16 + g + hs * 8;
            int bb = mg >> 11;
            int s  = mg & (SEQ - 1);
            unsigned int* orow = out + ((bb * NHEAD + h) * SEQ + s) * HDIM;
            #pragma unroll
            for (int nt = 0; nt < 4; nt++) {
                int d = wx * 32 + nt * 8 + 2 * t;
                uint2 v;
                v.x = f2tf((acc[mt][nt][hs * 2 + 0] + bias[n0 + d])     * osc);
                v.y = f2tf((acc[mt][nt][hs * 2 + 1] + bias[n0 + d + 1]) * osc);
                *reinterpret_cast<uint2*>(orow + d) = v;
            }
        }
    }
}

// ---------------------------------------------------------------------------
// Kernel 2: flash attention, tf32 tensor cores, persistent + dynamic queue.
// 256 thr (8 warps), BM=128 q rows, key tile 64. Warp w owns q rows
// [16w,16w+16). Q/K/P smem k-permuted (P8) -> LDS.64 fragment loads.
// All smem strides 72 (bank-conflict-free for the frag patterns).
// ---------------------------------------------------------------------------
__global__ __launch_bounds__(256, 2) void attn_kernel(
    const float* __restrict__ mask, float* __restrict__ out)
{
    extern __shared__ uint32_t sm4[];
    uint32_t* Qs = sm4;                 // [128][72] (cols P8-permuted)
    uint32_t* Ks = Qs + 128 * 72;       // [64][72]  (cols P8-permuted)
    uint32_t* Vs = Ks + 64 * 72;        // [64][72]  (plain [key][d])
    uint32_t* Ps = Vs + 64 * 72;        // [128][72] (cols P8-permuted)
    float*    Ms = (float*)(Ps + 128 * 72);  // [64] mask tile

    const int tid  = threadIdx.x;
    const int warp = tid >> 5;
    const int lane = tid & 31;
    const int g = lane >> 2;
    const int t = lane & 3;
    const int wbase = warp * 16;
    const int pc0 = P8(2 * t);       // {0,4,1,5}
    const int pc1 = P8(2 * t + 1);   // {2,6,3,7}

    int tile = blockIdx.x;
    while (tile < NTILES) {
        const int pair = tile >> 4;
        const int qt   = tile & (QTILES - 1);
        const int bb = pair / NHEAD;
        const int hh = pair % NHEAD;
        const int q0 = qt * 128;

        const unsigned int* __restrict__ Qg = g_q + (bb * NHEAD + hh) * SEQ * HDIM;
        const unsigned int* __restrict__ Kg = g_k + (bb * NHEAD + hh) * SEQ * HDIM;
        const unsigned int* __restrict__ Vg = g_v + (bb * NHEAD + hh) * SEQ * HDIM;

        __syncthreads();   // prior tile done with all smem
        // Load Q tile (128x64 tf32 bits, already scaled)
        {
            const uint4* Q4 = reinterpret_cast<const uint4*>(Qg + q0 * HDIM);
            #pragma unroll
            for (int e = 0; e < 8; e++) {
                int idx = tid + e * 256;
                int r = idx >> 4, c = (idx & 15) * 4;
                uint4 v = Q4[idx];
                uint32_t* row = Qs + r * 72;
                row[P8(c + 0)] = v.x; row[P8(c + 1)] = v.y;
                row[P8(c + 2)] = v.z; row[P8(c + 3)] = v.w;
            }
        }

        float o[8][4] = {};
        float m_run[2] = {-1e30f, -1e30f}, l_run[2] = {0.f, 0.f};

        for (int k0 = 0; k0 < SEQ; k0 += 64) {
            __syncthreads();
            {
                const uint4* K4 = reinterpret_cast<const uint4*>(Kg + k0 * HDIM);
                const uint4* V4 = reinterpret_cast<const uint4*>(Vg + k0 * HDIM);
                #pragma unroll
                for (int e = 0; e < 4; e++) {
                    int idx = tid + e * 256;
                    int r = idx >> 4, c = (idx & 15) * 4;
                    uint4 kv = K4[idx];
                    uint32_t* row = Ks + r * 72;
                    row[P8(c + 0)] = kv.x; row[P8(c + 1)] = kv.y;
                    row[P8(c + 2)] = kv.z; row[P8(c + 3)] = kv.w;
                    *reinterpret_cast<uint4*>(Vs + r * 72 + c) = V4[idx];
                }
                if (tid < 64) Ms[tid] = mask[bb * SEQ + k0 + tid];
            }
            __syncthreads();

            // ---- S = Q K^T : warp m16 x n64, k=64 ----
            float s[8][4] = {};
            #pragma unroll
            for (int kk = 0; kk < 8; kk++) {
                uint2 A02 = *reinterpret_cast<const uint2*>(
                    Qs + (wbase + g) * 72 + kk * 8 + 2 * t);       // a0,a2
                uint2 A13 = *reinterpret_cast<const uint2*>(
                    Qs + (wbase + g + 8) * 72 + kk * 8 + 2 * t);   // a1,a3
                #pragma unroll
                for (int nt = 0; nt < 8; nt++) {
                    uint2 B01 = *reinterpret_cast<const uint2*>(
                        Ks + (nt * 8 + g) * 72 + kk * 8 + 2 * t);
                    mma8(s[nt], A02.x, A13.x, A02.y, A13.y, B01.x, B01.y);
                }
            }

            // ---- online softmax (rows wbase+g, wbase+g+8) ----
            float2 mk2[8];
            #pragma unroll
            for (int nt = 0; nt < 8; nt++)
                mk2[nt] = *reinterpret_cast<const float2*>(Ms + nt * 8 + 2 * t);

            #pragma unroll
            for (int hs = 0; hs < 2; hs++) {
                float mm = -1e30f;
                #pragma unroll
                for (int nt = 0; nt < 8; nt++) {
                    float v0 = s[nt][hs * 2 + 0] + mk2[nt].x;
                    float v1 = s[nt][hs * 2 + 1] + mk2[nt].y;
                    s[nt][hs * 2 + 0] = v0;
                    s[nt][hs * 2 + 1] = v1;
                    mm = fmaxf(mm, fmaxf(v0, v1));
                }
                mm = fmaxf(mm, __shfl_xor_sync(0xffffffffu, mm, 1));
                mm = fmaxf(mm, __shfl_xor_sync(0xffffffffu, mm, 2));

                float mn = fmaxf(m_run[hs], mm);
                float alpha = __expf(m_run[hs] - mn);
                m_run[hs] = mn;

                float ps = 0.f;
                #pragma unroll
                for (int nt = 0; nt < 8; nt++) {
                    float p0 = __expf(s[nt][hs * 2 + 0] - mn);
                    float p1 = __expf(s[nt][hs * 2 + 1] - mn);
                    s[nt][hs * 2 + 0] = p0;
                    s[nt][hs * 2 + 1] = p1;
                    ps += p0 + p1;
                }
                ps += __shfl_xor_sync(0xffffffffu, ps, 1);
                ps += __shfl_xor_sync(0xffffffffu, ps, 2);
                l_run[hs] = l_run[hs] * alpha + ps;

                #pragma unroll
                for (int nt = 0; nt < 8; nt++) {
                    o[nt][hs * 2 + 0] *= alpha;
                    o[nt][hs * 2 + 1] *= alpha;
                }
            }

            // ---- stage P (tf32, permuted cols): own warp's 16 rows ----
            {
                uint32_t* pr0 = Ps + (wbase + g) * 72;
                uint32_t* pr1 = Ps + (wbase + g + 8) * 72;
                #pragma unroll
                for (int nt = 0; nt < 8; nt++) {
                    pr0[nt * 8 + pc0] = f2tf(s[nt][0]);
                    pr0[nt * 8 + pc1] = f2tf(s[nt][1]);
                    pr1[nt * 8 + pc0] = f2tf(s[nt][2]);
                    pr1[nt * 8 + pc1] = f2tf(s[nt][3]);
                }
            }
            __syncwarp();

            // ---- O += P V : warp m16 x n64, k=64 (keys) ----
            #pragma unroll
            for (int kk = 0; kk < 8; kk++) {
                uint2 A02 = *reinterpret_cast<const uint2*>(
                    Ps + (wbase + g) * 72 + kk * 8 + 2 * t);
                uint2 A13 = *reinterpret_cast<const uint2*>(
                    Ps + (wbase + g + 8) * 72 + kk * 8 + 2 * t);
                #pragma unroll
                for (int nt = 0; nt < 8; nt++) {
                    uint32_t b0 = Vs[(kk * 8 + t) * 72 + nt * 8 + g];
                    uint32_t b1 = Vs[(kk * 8 + t + 4) * 72 + nt * 8 + g];
                    mma8(o[nt], A02.x, A13.x, A02.y, A13.y, b0, b1);
                }
            }
        }

        // ---- normalize + write out [B,S,D] ----
        #pragma unroll
        for (int hs = 0; hs < 2; hs++) {
            int r = q0 + wbase + g + hs * 8;
            float inv = 1.f / l_run[hs];
            float* orow = out + (bb * SEQ + r) * DMODEL + hh * HDIM;
            #pragma unroll
            for (int nt = 0; nt < 8; nt++) {
                float2 v;
                v.x = o[nt][hs * 2 + 0] * inv;
                v.y = o[nt][hs * 2 + 1] * inv;
                *reinterpret_cast<float2*>(orow + nt * 8 + 2 * t) = v;
            }
        }

        // next tile from dynamic queue
        if (tid == 0)
            *((unsigned int*)Ms) = atomicAdd(&g_ctr, 1u);
        __syncthreads();
        tile = *((unsigned int*)Ms);
    }
}

// ---------------------------------------------------------------------------
extern "C" void kernel_launch(void* const* d_in, const int* in_sizes, int n_in,
                              void* d_out, int out_size)
{
    const float* v1   = (const float*)d_in[0];
    const float* mask = (const float*)d_in[1];
    const float* Wq   = (const float*)d_in[2];
    const float* bq   = (const float*)d_in[3];
    const float* Wk   = (const float*)d_in[4];
    const float* bk   = (const float*)d_in[5];
    const float* Wv   = (const float*)d_in[6];
    const float* bv   = (const float*)d_in[7];
    float* out = (float*)d_out;

    dim3 g1(DMODEL / 64, MROWS / 128, 3);
    qkv_kernel<<<g1, 256>>>(v1, Wq, bq, Wk, bk, Wv, bv);

    // smem: (128+64+64+128)*72*4 + 256 = 110848 B
    const int smem_bytes = (128 * 72 + 64 * 72 + 64 * 72 + 128 * 72) * 4 + 256;
    cudaFuncSetAttribute(attn_kernel, cudaFuncAttributeMaxDynamicSharedMemorySize,
                         smem_bytes);
    attn_kernel<<<ATTN_GRID, 256, smem_bytes>>>(mask, out);
}

// round 14
// speedup vs baseline: 1.5151x; 1.5151x over previous
#include <cuda_runtime.h>
#include <cuda_fp16.h>
#include <cstdint>

#define BATCH 2
#define SEQ   2048
#define DMODEL 768
#define NHEAD 12
#define HDIM  64
#define MROWS (BATCH*SEQ)            // 4096
#define QTILES (SEQ/128)             // 16
#define NTILES (QTILES*BATCH*NHEAD)  // 384
#define ATTN_GRID 296                // 2 CTAs x 148 SMs

// Scratch in fp16: Q [B,H,S,hd] pre-scaled 1/8, K [B,H,S,hd], V [B,H,hd,S] (transposed)
__device__ __half g_q[BATCH*NHEAD*SEQ*HDIM];
__device__ __half g_k[BATCH*NHEAD*SEQ*HDIM];
__device__ __half g_v[BATCH*NHEAD*SEQ*HDIM];

// ---------------------------------------------------------------------------
// helpers
// ---------------------------------------------------------------------------
__device__ __forceinline__ uint32_t pack2(float a, float b) {
    __half2 h = __floats2half2_rn(a, b);
    return *reinterpret_cast<uint32_t*>(&h);
}
// hi/lo fp16 split of two consecutive values, packed
__device__ __forceinline__ void split2(float v0, float v1,
                                       uint32_t& hi, uint32_t& lo) {
    __half h0 = __float2half_rn(v0), h1 = __float2half_rn(v1);
    __half l0 = __float2half_rn(v0 - __half2float(h0));
    __half l1 = __float2half_rn(v1 - __half2float(h1));
    __half2 H = __halves2half2(h0, h1), L = __halves2half2(l0, l1);
    hi = *reinterpret_cast<uint32_t*>(&H);
    lo = *reinterpret_cast<uint32_t*>(&L);
}
// D += A(m16k16,row) * B(k16n8,col), fp16 inputs, fp32 accum
__device__ __forceinline__ void mma16(float* c,
    uint32_t a0, uint32_t a1, uint32_t a2, uint32_t a3,
    uint32_t b0, uint32_t b1)
{
    asm volatile(
        "mma.sync.aligned.m16n8k16.row.col.f32.f16.f16.f32 "
        "{%0,%1,%2,%3}, {%4,%5,%6,%7}, {%8,%9}, {%0,%1,%2,%3};"
        : "+f"(c[0]), "+f"(c[1]), "+f"(c[2]), "+f"(c[3])
        : "r"(a0), "r"(a1), "r"(a2), "r"(a3), "r"(b0), "r"(b1));
}

// ---------------------------------------------------------------------------
// Kernel 1: QKV projection, 2xFP16 split (hh+hl+lh, ~fp32 accuracy).
// 256 thr (8 warps: wy 0..3, wx 0..1), BM=128, BN=64, BK=16 (one k16 mma step).
// A smem [m][kpair] stride 12 u32; B smem [n][kpair] stride 12 u32 (transposed
// via 16-bit stores). Outputs fp16: Q scaled 1/8; V written transposed.
// ---------------------------------------------------------------------------
__global__ __launch_bounds__(256, 3) void qkv_kernel(
    const float* __restrict__ X,
    const float* __restrict__ Wq, const float* __restrict__ bq,
    const float* __restrict__ Wk, const float* __restrict__ bk,
    const float* __restrict__ Wv, const float* __restrict__ bv)
{
    const int z = blockIdx.z;
    const float* __restrict__ W    = (z == 0) ? Wq : (z == 1) ? Wk : Wv;
    const float* __restrict__ bias = (z == 0) ? bq : (z == 1) ? bk : bv;
    __half* __restrict__ out       = (z == 0) ? g_q : (z == 1) ? g_k : g_v;
    const float osc = (z == 0) ? 0.125f : 1.0f;

    __shared__ uint32_t Ah[128 * 12], Al[128 * 12];   // [m][kpair], pad 8->12
    __shared__ uint32_t Bh[64 * 12],  Bl[64 * 12];    // [n][kpair]

    const int tid  = threadIdx.x;
    const int warp = tid >> 5;
    const int lane = tid & 31;
    const int g = lane >> 2;
    const int t = lane & 3;
    const int wy = warp >> 1;
    const int wx = warp & 1;

    const int m0 = blockIdx.y * 128;
    const int n0 = blockIdx.x * 64;

    const int rB  = tid & 15;     // k row for B loads
    const int cB4 = tid >> 4;     // n chunk (0..15, 4 cols each)

    float acc[2][4][4] = {};
    float4 pa[2], pb;

    // prefetch first tile
    #pragma unroll
    for (int e = 0; e < 2; e++) {
        int idx = tid + e * 256;
        pa[e] = *reinterpret_cast<const float4*>(
            X + (m0 + (idx & 127)) * DMODEL + 4 * (idx >> 7));
    }
    pb = *reinterpret_cast<const float4*>(W + rB * DMODEL + n0 + 4 * cB4);

    for (int k0 = 0; k0 < DMODEL; k0 += 16) {
        __syncthreads();   // previous mma step done reading smem
        // store A splits: row m, pair cols 2c4, 2c4+1
        #pragma unroll
        for (int e = 0; e < 2; e++) {
            int idx = tid + e * 256;
            int r = idx & 127, c4 = idx >> 7;
            const float* v = reinterpret_cast<const float*>(&pa[e]);
            uint2 H, L;
            split2(v[0], v[1], H.x, L.x);
            split2(v[2], v[3], H.y, L.y);
            *reinterpret_cast<uint2*>(Ah + r * 12 + 2 * c4) = H;
            *reinterpret_cast<uint2*>(Al + r * 12 + 2 * c4) = L;
        }
        // store B splits transposed: [n][kpair], 16-bit stores
        {
            __half* BhH = reinterpret_cast<__half*>(Bh);
            __half* BlH = reinterpret_cast<__half*>(Bl);
            const float* v = reinterpret_cast<const float*>(&pb);
            int off = (rB >> 1) * 2 + (rB & 1);
            #pragma unroll
            for (int j = 0; j < 4; j++) {
                int n = 4 * cB4 + j;
                __half h = __float2half_rn(v[j]);
                __half l = __float2half_rn(v[j] - __half2float(h));
                BhH[n * 24 + off] = h;
                BlH[n * 24 + off] = l;
            }
        }
        __syncthreads();

        // prefetch next tile (overlaps mma step)
        if (k0 + 16 < DMODEL) {
            #pragma unroll
            for (int e = 0; e < 2; e++) {
                int idx = tid + e * 256;
                pa[e] = *reinterpret_cast<const float4*>(
                    X + (m0 + (idx & 127)) * DMODEL + k0 + 16 + 4 * (idx >> 7));
            }
            pb = *reinterpret_cast<const float4*>(
                W + (k0 + 16 + rB) * DMODEL + n0 + 4 * cB4);
        }

        // one k16 mma step
        uint32_t ah[2][4], al[2][4];
        #pragma unroll
        for (int mt = 0; mt < 2; mt++) {
            int rb = wy * 32 + mt * 16;
            ah[mt][0] = Ah[(rb + g) * 12 + t];
            ah[mt][1] = Ah[(rb + g + 8) * 12 + t];
            ah[mt][2] = Ah[(rb + g) * 12 + t + 4];
            ah[mt][3] = Ah[(rb + g + 8) * 12 + t + 4];
            al[mt][0] = Al[(rb + g) * 12 + t];
            al[mt][1] = Al[(rb + g + 8) * 12 + t];
            al[mt][2] = Al[(rb + g) * 12 + t + 4];
            al[mt][3] = Al[(rb + g + 8) * 12 + t + 4];
        }
        #pragma unroll
        for (int nt = 0; nt < 4; nt++) {
            int nr = wx * 32 + nt * 8 + g;
            uint32_t bh0 = Bh[nr * 12 + t], bh1 = Bh[nr * 12 + t + 4];
            uint32_t bl0 = Bl[nr * 12 + t], bl1 = Bl[nr * 12 + t + 4];
            #pragma unroll
            for (int mt = 0; mt < 2; mt++) {
                mma16(acc[mt][nt], ah[mt][0], ah[mt][1], ah[mt][2], ah[mt][3], bh0, bh1);
                mma16(acc[mt][nt], ah[mt][0], ah[mt][1], ah[mt][2], ah[mt][3], bl0, bl1);
                mma16(acc[mt][nt], al[mt][0], al[mt][1], al[mt][2], al[mt][3], bh0, bh1);
            }
        }
    }

    // Epilogue: +bias, scale, fp16. Q/K -> [B,H,S,hd]; V -> [B,H,hd,S].
    const int h = n0 >> 6;
    #pragma unroll
    for (int mt = 0; mt < 2; mt++) {
        #pragma unroll
        for (int hs = 0; hs < 2; hs++) {
            int mg = m0 + wy * 32 + mt * 16 + g + hs * 8;
            int bb = mg >> 11;
            int s  = mg & (SEQ - 1);
            #pragma unroll
            for (int nt = 0; nt < 4; nt++) {
                int d = wx * 32 + nt * 8 + 2 * t;
                float v0 = (acc[mt][nt][hs * 2 + 0] + bias[n0 + d])     * osc;
                float v1 = (acc[mt][nt][hs * 2 + 1] + bias[n0 + d + 1]) * osc;
                if (z == 2) {
                    __half* vb = out + (bb * NHEAD + h) * HDIM * SEQ;
                    vb[(d)     * SEQ + s] = __float2half_rn(v0);
                    vb[(d + 1) * SEQ + s] = __float2half_rn(v1);
                } else {
                    uint32_t* orow = reinterpret_cast<uint32_t*>(
                        out + ((bb * NHEAD + h) * SEQ + s) * HDIM);
                    orow[d >> 1] = pack2(v0, v1);
                }
            }
        }
    }
}

// ---------------------------------------------------------------------------
// Kernel 2: flash attention, fp16 m16n8k16, persistent with STATIC round-robin
// tile assignment (uniform tile cost -> same makespan as a dynamic queue,
// zero atomics, fully deterministic).
// 256 thr (8 warps), BM=128 q rows, key tile 64. Warp w owns q rows
// [16w,16w+16). Q fragments register-resident (loaded once per tile).
// smem: K [key][dpair], V [d][keypair] (from transposed g_v), P [row][keypair],
// all stride 36 u32 (conflict-free 4g+t pattern).
// ---------------------------------------------------------------------------
__global__ __launch_bounds__(256, 2) void attn_kernel(
    const float* __restrict__ mask, float* __restrict__ out)
{
    extern __shared__ uint32_t sm4[];
    uint32_t* Ks = sm4;                 // [64][36]
    uint32_t* Vs = Ks + 64 * 36;        // [64][36]
    uint32_t* Ps = Vs + 64 * 36;        // [128][36]
    float*    Ms = (float*)(Ps + 128 * 36);       // [64] mask

    const int tid  = threadIdx.x;
    const int warp = tid >> 5;
    const int lane = tid & 31;
    const int g = lane >> 2;
    const int t = lane & 3;
    const int wbase = warp * 16;

    for (int tile = blockIdx.x; tile < NTILES; tile += ATTN_GRID) {
        const int pair = tile >> 4;
        const int qt   = tile & (QTILES - 1);
        const int bb = pair / NHEAD;
        const int hh = pair % NHEAD;
        const int q0 = qt * 128;

        const uint32_t* Qw = reinterpret_cast<const uint32_t*>(g_q)
                           + (bb * NHEAD + hh) * SEQ * (HDIM / 2);
        const __half* Kg = g_k + (bb * NHEAD + hh) * SEQ * HDIM;
        const __half* Vg = g_v + (bb * NHEAD + hh) * HDIM * SEQ;

        // Q fragments -> registers (one warp-tile per warp, reused all k-tiles)
        uint32_t qa[4][4];
        {
            int r0 = (q0 + wbase + g) * 32;
            int r1 = r0 + 8 * 32;
            #pragma unroll
            for (int kk = 0; kk < 4; kk++) {
                qa[kk][0] = Qw[r0 + kk * 8 + t];
                qa[kk][1] = Qw[r1 + kk * 8 + t];
                qa[kk][2] = Qw[r0 + kk * 8 + t + 4];
                qa[kk][3] = Qw[r1 + kk * 8 + t + 4];
            }
        }

        float o[8][4] = {};
        float m_run[2] = {-1e30f, -1e30f}, l_run[2] = {0.f, 0.f};

        for (int k0 = 0; k0 < SEQ; k0 += 64) {
            __syncthreads();   // prev iter (or prev tile) done with Ks/Vs/Ps
            {
                const uint4* K4 = reinterpret_cast<const uint4*>(Kg);
                const uint4* V4 = reinterpret_cast<const uint4*>(Vg);
                #pragma unroll
                for (int e = 0; e < 2; e++) {
                    int idx = tid + e * 256;          // 512 uint4 total
                    int r = idx >> 3, c = idx & 7;
                    uint4 kv = K4[(k0 + r) * 8 + c];  // K row r, 8 d-pairs
                    *reinterpret_cast<uint2*>(Ks + r * 36 + c * 4)     = make_uint2(kv.x, kv.y);
                    *reinterpret_cast<uint2*>(Ks + r * 36 + c * 4 + 2) = make_uint2(kv.z, kv.w);
                    uint4 vv = V4[r * (SEQ / 8) + (k0 >> 3) + c];  // V d-row r, 8 key-pairs
                    *reinterpret_cast<uint2*>(Vs + r * 36 + c * 4)     = make_uint2(vv.x, vv.y);
                    *reinterpret_cast<uint2*>(Vs + r * 36 + c * 4 + 2) = make_uint2(vv.z, vv.w);
                }
                if (tid < 64) Ms[tid] = mask[bb * SEQ + k0 + tid];
            }
            __syncthreads();

            // ---- S = Q K^T : warp m16 x n64, k=64 (4 k16 steps) ----
            float s[8][4] = {};
            #pragma unroll
            for (int kk = 0; kk < 4; kk++) {
                #pragma unroll
                for (int nt = 0; nt < 8; nt++) {
                    const uint32_t* kr = Ks + (nt * 8 + g) * 36 + kk * 8;
                    mma16(s[nt], qa[kk][0], qa[kk][1], qa[kk][2], qa[kk][3],
                          kr[t], kr[t + 4]);
                }
            }

            // ---- online softmax (rows wbase+g, wbase+g+8) ----
            float2 mk2[8];
            #pragma unroll
            for (int nt = 0; nt < 8; nt++)
                mk2[nt] = *reinterpret_cast<const float2*>(Ms + nt * 8 + 2 * t);

            #pragma unroll
            for (int hs = 0; hs < 2; hs++) {
                float mm = -1e30f;
                #pragma unroll
                for (int nt = 0; nt < 8; nt++) {
                    float v0 = s[nt][hs * 2 + 0] + mk2[nt].x;
                    float v1 = s[nt][hs * 2 + 1] + mk2[nt].y;
                    s[nt][hs * 2 + 0] = v0;
                    s[nt][hs * 2 + 1] = v1;
                    mm = fmaxf(mm, fmaxf(v0, v1));
                }
                mm = fmaxf(mm, __shfl_xor_sync(0xffffffffu, mm, 1));
                mm = fmaxf(mm, __shfl_xor_sync(0xffffffffu, mm, 2));

                float mn = fmaxf(m_run[hs], mm);
                float alpha = __expf(m_run[hs] - mn);
                m_run[hs] = mn;

                float ps = 0.f;
                #pragma unroll
                for (int nt = 0; nt < 8; nt++) {
                    float p0 = __expf(s[nt][hs * 2 + 0] - mn);
                    float p1 = __expf(s[nt][hs * 2 + 1] - mn);
                    s[nt][hs * 2 + 0] = p0;
                    s[nt][hs * 2 + 1] = p1;
                    ps += p0 + p1;
                }
                ps += __shfl_xor_sync(0xffffffffu, ps, 1);
                ps += __shfl_xor_sync(0xffffffffu, ps, 2);
                l_run[hs] = l_run[hs] * alpha + ps;

                #pragma unroll
                for (int nt = 0; nt < 8; nt++) {
                    o[nt][hs * 2 + 0] *= alpha;
                    o[nt][hs * 2 + 1] *= alpha;
                }
            }

            // ---- stage P (fp16x2): own warp's 16 rows ----
            {
                uint32_t* pr0 = Ps + (wbase + g) * 36;
                uint32_t* pr1 = pr0 + 8 * 36;
                #pragma unroll
                for (int nt = 0; nt < 8; nt++) {
                    pr0[nt * 4 + t] = pack2(s[nt][0], s[nt][1]);
                    pr1[nt * 4 + t] = pack2(s[nt][2], s[nt][3]);
                }
            }
            __syncwarp();

            // ---- O += P V : warp m16 x n64, k=64 keys (4 k16 steps) ----
            #pragma unroll
            for (int kk = 0; kk < 4; kk++) {
                const uint32_t* p0p = Ps + (wbase + g) * 36 + kk * 8;
                const uint32_t* p1p = p0p + 8 * 36;
                uint32_t a0 = p0p[t],     a1 = p1p[t];
                uint32_t a2 = p0p[t + 4], a3 = p1p[t + 4];
                #pragma unroll
                for (int nt = 0; nt < 8; nt++) {
                    const uint32_t* vr = Vs + (nt * 8 + g) * 36 + kk * 8;
                    mma16(o[nt], a0, a1, a2, a3, vr[t], vr[t + 4]);
                }
            }
        }

        // ---- normalize + write out [B,S,D] ----
        #pragma unroll
        for (int hs = 0; hs < 2; hs++) {
            int r = q0 + wbase + g + hs * 8;
            float inv = 1.f / l_run[hs];
            float* orow = out + (bb * SEQ + r) * DMODEL + hh * HDIM;
            #pragma unroll
            for (int nt = 0; nt < 8; nt++) {
                float2 v;
                v.x = o[nt][hs * 2 + 0] * inv;
                v.y = o[nt][hs * 2 + 1] * inv;
                *reinterpret_cast<float2*>(orow + nt * 8 + 2 * t) = v;
            }
        }
    }
}

// ---------------------------------------------------------------------------
extern "C" void kernel_launch(void* const* d_in, const int* in_sizes, int n_in,
                              void* d_out, int out_size)
{
    const float* v1   = (const float*)d_in[0];
    const float* mask = (const float*)d_in[1];
    const float* Wq   = (const float*)d_in[2];
    const float* bq   = (const float*)d_in[3];
    const float* Wk   = (const float*)d_in[4];
    const float* bk   = (const float*)d_in[5];
    const float* Wv   = (const float*)d_in[6];
    const float* bv   = (const float*)d_in[7];
    float* out = (float*)d_out;

    dim3 g1(DMODEL / 64, MROWS / 128, 3);
    qkv_kernel<<<g1, 256>>>(v1, Wq, bq, Wk, bk, Wv, bv);

    // smem: (64+64+128)*36*4 + 64*4 = 37120 B
    const int smem_bytes = (64 * 36 + 64 * 36 + 128 * 36) * 4 + 64 * 4;
    cudaFuncSetAttribute(attn_kernel, cudaFuncAttributeMaxDynamicSharedMemorySize,
                         smem_bytes);
    attn_kernel<<<ATTN_GRID, 256, smem_bytes>>>(mask, out);
}

// round 15
// speedup vs baseline: 1.6831x; 1.1109x over previous
#include <cuda_runtime.h>
#include <cuda_fp16.h>
#include <cstdint>

#define BATCH 2
#define SEQ   2048
#define DMODEL 768
#define NHEAD 12
#define HDIM  64
#define MROWS (BATCH*SEQ)            // 4096
#define QTILES (SEQ/128)             // 16
#define NTILES (QTILES*BATCH*NHEAD)  // 384
#define ATTN_GRID 296                // 2 CTAs x 148 SMs

// Pre-split inputs (fp16 hi/lo). Wt is transposed: [z][n][k].
__device__ __half g_xh[MROWS*DMODEL], g_xl[MROWS*DMODEL];
__device__ __half g_wh[3*DMODEL*DMODEL], g_wl[3*DMODEL*DMODEL];
// Scratch fp16: Q [B,H,S,hd] pre-scaled 1/8, K [B,H,S,hd], V [B,H,hd,S]
__device__ __half g_q[BATCH*NHEAD*SEQ*HDIM];
__device__ __half g_k[BATCH*NHEAD*SEQ*HDIM];
__device__ __half g_v[BATCH*NHEAD*SEQ*HDIM];

// ---------------------------------------------------------------------------
// helpers
// ---------------------------------------------------------------------------
__device__ __forceinline__ uint32_t pack2(float a, float b) {
    __half2 h = __floats2half2_rn(a, b);
    return *reinterpret_cast<uint32_t*>(&h);
}
__device__ __forceinline__ void splith(float v, __half& h, __half& l) {
    h = __float2half_rn(v);
    l = __float2half_rn(v - __half2float(h));
}
// D += A(m16k16,row) * B(k16n8,col), fp16 inputs, fp32 accum
__device__ __forceinline__ void mma16(float* c,
    uint32_t a0, uint32_t a1, uint32_t a2, uint32_t a3,
    uint32_t b0, uint32_t b1)
{
    asm volatile(
        "mma.sync.aligned.m16n8k16.row.col.f32.f16.f16.f32 "
        "{%0,%1,%2,%3}, {%4,%5,%6,%7}, {%8,%9}, {%0,%1,%2,%3};"
        : "+f"(c[0]), "+f"(c[1]), "+f"(c[2]), "+f"(c[3])
        : "r"(a0), "r"(a1), "r"(a2), "r"(a3), "r"(b0), "r"(b1));
}

// ---------------------------------------------------------------------------
// Kernel 0a: split X into fp16 hi/lo (once, instead of 36x inline in GEMM)
// ---------------------------------------------------------------------------
__global__ __launch_bounds__(256) void convx_kernel(const float* __restrict__ X)
{
    int i = blockIdx.x * 256 + threadIdx.x;     // float4 index, 786432 total
    float4 v = reinterpret_cast<const float4*>(X)[i];
    __half h0, l0, h1, l1, h2, l2, h3, l3;
    splith(v.x, h0, l0); splith(v.y, h1, l1);
    splith(v.z, h2, l2); splith(v.w, h3, l3);
    __half2 H0 = __halves2half2(h0, h1), H1 = __halves2half2(h2, h3);
    __half2 L0 = __halves2half2(l0, l1), L1 = __halves2half2(l2, l3);
    uint2 H = make_uint2(*(uint32_t*)&H0, *(uint32_t*)&H1);
    uint2 L = make_uint2(*(uint32_t*)&L0, *(uint32_t*)&L1);
    reinterpret_cast<uint2*>(g_xh)[i] = H;
    reinterpret_cast<uint2*>(g_xl)[i] = L;
}

// ---------------------------------------------------------------------------
// Kernel 0b: transpose + split W -> Wt[z][n][k] fp16 hi/lo. 32x32 tiles.
// ---------------------------------------------------------------------------
__global__ __launch_bounds__(256) void convw_kernel(
    const float* __restrict__ Wq, const float* __restrict__ Wk,
    const float* __restrict__ Wv)
{
    const int z = blockIdx.z;
    const float* __restrict__ W = (z == 0) ? Wq : (z == 1) ? Wk : Wv;
    __shared__ float tile[32][33];
    const int k0 = blockIdx.x * 32, n0 = blockIdx.y * 32;
    const int tx = threadIdx.x & 31, ty = threadIdx.x >> 5;   // 32 x 8
    #pragma unroll
    for (int j = 0; j < 4; j++)
        tile[ty * 4 + j][tx] = W[(k0 + ty * 4 + j) * DMODEL + n0 + tx];
    __syncthreads();
    #pragma unroll
    for (int j = 0; j < 4; j++) {
        int n = n0 + ty * 4 + j;
        float v = tile[tx][ty * 4 + j];
        __half h, l; splith(v, h, l);
        g_wh[z * DMODEL * DMODEL + n * DMODEL + k0 + tx] = h;
        g_wl[z * DMODEL * DMODEL + n * DMODEL + k0 + tx] = l;
    }
}

// ---------------------------------------------------------------------------
// Kernel 1: QKV projection GEMM, 2xFP16 split (hh+hl+lh), zero conversions in
// the hot loop (pure uint4 copies from pre-split arrays). 256 thr (8 warps),
// BM=128, BN=64, BK=32 (two k16 steps/iter). smem strides 20 u32 (conflict-
// free fragment pattern). Outputs fp16: Q scaled 1/8; V transposed [B,H,hd,S].
// ---------------------------------------------------------------------------
__global__ __launch_bounds__(256, 2) void qkv_kernel(
    const float* __restrict__ bq, const float* __restrict__ bk,
    const float* __restrict__ bv)
{
    const int z = blockIdx.z;
    const float* __restrict__ bias = (z == 0) ? bq : (z == 1) ? bk : bv;
    __half* __restrict__ out       = (z == 0) ? g_q : (z == 1) ? g_k : g_v;
    const float osc = (z == 0) ? 0.125f : 1.0f;

    __shared__ uint32_t Ah[128 * 20], Al[128 * 20];   // [m][kpair(16)] pad 20
    __shared__ uint32_t Bh[64 * 20],  Bl[64 * 20];    // [n][kpair(16)] pad 20

    const int tid  = threadIdx.x;
    const int warp = tid >> 5;
    const int lane = tid & 31;
    const int g = lane >> 2;
    const int t = lane & 3;
    const int wy = warp >> 1;         // 0..3
    const int wx = warp & 1;          // 0..1

    const int m0 = blockIdx.y * 128;
    const int n0 = blockIdx.x * 64;

    const uint4* Xh4 = reinterpret_cast<const uint4*>(g_xh);
    const uint4* Xl4 = reinterpret_cast<const uint4*>(g_xl);
    const uint4* Wh4 = reinterpret_cast<const uint4*>(g_wh + z * DMODEL * DMODEL);
    const uint4* Wl4 = reinterpret_cast<const uint4*>(g_wl + z * DMODEL * DMODEL);

    // A: 128m x 32k halves = 512 uint4/array -> 2/thread. r=idx&127, c8=idx>>7
    // B: 64n  x 32k halves = 256 uint4/array -> 1/thread. nr=tid>>2, c8=tid&3
    const int rA0 = tid & 127, cA0 = tid >> 7;          // e=0
    const int rA1 = rA0, cA1 = cA0 + 2;                 // e=1 (tid+256)
    const int nB = tid >> 2, cB = tid & 3;

    float acc[2][4][4] = {};
    uint4 pah[2], pal[2], pbh, pbl;

    // prefetch first tile
    pah[0] = Xh4[(m0 + rA0) * 96 + cA0]; pal[0] = Xl4[(m0 + rA0) * 96 + cA0];
    pah[1] = Xh4[(m0 + rA1) * 96 + cA1]; pal[1] = Xl4[(m0 + rA1) * 96 + cA1];
    pbh = Wh4[(n0 + nB) * 96 + cB];      pbl = Wl4[(n0 + nB) * 96 + cB];

    for (int k0 = 0; k0 < DMODEL; k0 += 32) {
        __syncthreads();   // previous mma phase done reading smem
        *reinterpret_cast<uint4*>(Ah + rA0 * 20 + cA0 * 4) = pah[0];
        *reinterpret_cast<uint4*>(Al + rA0 * 20 + cA0 * 4) = pal[0];
        *reinterpret_cast<uint4*>(Ah + rA1 * 20 + cA1 * 4) = pah[1];
        *reinterpret_cast<uint4*>(Al + rA1 * 20 + cA1 * 4) = pal[1];
        *reinterpret_cast<uint4*>(Bh + nB * 20 + cB * 4) = pbh;
        *reinterpret_cast<uint4*>(Bl + nB * 20 + cB * 4) = pbl;
        __syncthreads();

        // prefetch next tile (overlaps mma phase)
        if (k0 + 32 < DMODEL) {
            int kb = (k0 + 32) >> 3;
            pah[0] = Xh4[(m0 + rA0) * 96 + kb + cA0];
            pal[0] = Xl4[(m0 + rA0) * 96 + kb + cA0];
            pah[1] = Xh4[(m0 + rA1) * 96 + kb + cA1];
            pal[1] = Xl4[(m0 + rA1) * 96 + kb + cA1];
            pbh = Wh4[(n0 + nB) * 96 + kb + cB];
            pbl = Wl4[(n0 + nB) * 96 + kb + cB];
        }

        #pragma unroll
        for (int kk = 0; kk < 2; kk++) {
            uint32_t ah[2][4], al[2][4];
            #pragma unroll
            for (int mt = 0; mt < 2; mt++) {
                int r0 = (wy * 32 + mt * 16 + g) * 20 + kk * 8;
                int r1 = r0 + 8 * 20;
                ah[mt][0] = Ah[r0 + t];     ah[mt][1] = Ah[r1 + t];
                ah[mt][2] = Ah[r0 + t + 4]; ah[mt][3] = Ah[r1 + t + 4];
                al[mt][0] = Al[r0 + t];     al[mt][1] = Al[r1 + t];
                al[mt][2] = Al[r0 + t + 4]; al[mt][3] = Al[r1 + t + 4];
            }
            #pragma unroll
            for (int nt = 0; nt < 4; nt++) {
                int nr = (wx * 32 + nt * 8 + g) * 20 + kk * 8;
                uint32_t bh0 = Bh[nr + t], bh1 = Bh[nr + t + 4];
                uint32_t bl0 = Bl[nr + t], bl1 = Bl[nr + t + 4];
                #pragma unroll
                for (int mt = 0; mt < 2; mt++) {
                    mma16(acc[mt][nt], ah[mt][0], ah[mt][1], ah[mt][2], ah[mt][3], bh0, bh1);
                    mma16(acc[mt][nt], ah[mt][0], ah[mt][1], ah[mt][2], ah[mt][3], bl0, bl1);
                    mma16(acc[mt][nt], al[mt][0], al[mt][1], al[mt][2], al[mt][3], bh0, bh1);
                }
            }
        }
    }

    // Epilogue: +bias, scale, fp16. Q/K -> [B,H,S,hd]; V -> [B,H,hd,S].
    const int h = n0 >> 6;
    #pragma unroll
    for (int mt = 0; mt < 2; mt++) {
        #pragma unroll
        for (int hs = 0; hs < 2; hs++) {
            int mg = m0 + wy * 32 + mt * 16 + g + hs * 8;
            int bb = mg >> 11;
            int s  = mg & (SEQ - 1);
            #pragma unroll
            for (int nt = 0; nt < 4; nt++) {
                int d = wx * 32 + nt * 8 + 2 * t;
                float v0 = (acc[mt][nt][hs * 2 + 0] + bias[n0 + d])     * osc;
                float v1 = (acc[mt][nt][hs * 2 + 1] + bias[n0 + d + 1]) * osc;
                if (z == 2) {
                    __half* vb = out + (bb * NHEAD + h) * HDIM * SEQ;
                    vb[(d)     * SEQ + s] = __float2half_rn(v0);
                    vb[(d + 1) * SEQ + s] = __float2half_rn(v1);
                } else {
                    uint32_t* orow = reinterpret_cast<uint32_t*>(
                        out + ((bb * NHEAD + h) * SEQ + s) * HDIM);
                    orow[d >> 1] = pack2(v0, v1);
                }
            }
        }
    }
}

// ---------------------------------------------------------------------------
// Kernel 2: flash attention, fp16 m16n8k16, persistent static round-robin.
// (unchanged from the 139.6us R14 version)
// ---------------------------------------------------------------------------
__global__ __launch_bounds__(256, 2) void attn_kernel(
    const float* __restrict__ mask, float* __restrict__ out)
{
    extern __shared__ uint32_t sm4[];
    uint32_t* Ks = sm4;                 // [64][36]
    uint32_t* Vs = Ks + 64 * 36;        // [64][36]
    uint32_t* Ps = Vs + 64 * 36;        // [128][36]
    float*    Ms = (float*)(Ps + 128 * 36);       // [64] mask

    const int tid  = threadIdx.x;
    const int warp = tid >> 5;
    const int lane = tid & 31;
    const int g = lane >> 2;
    const int t = lane & 3;
    const int wbase = warp * 16;

    for (int tile = blockIdx.x; tile < NTILES; tile += ATTN_GRID) {
        const int pair = tile >> 4;
        const int qt   = tile & (QTILES - 1);
        const int bb = pair / NHEAD;
        const int hh = pair % NHEAD;
        const int q0 = qt * 128;

        const uint32_t* Qw = reinterpret_cast<const uint32_t*>(g_q)
                           + (bb * NHEAD + hh) * SEQ * (HDIM / 2);
        const __half* Kg = g_k + (bb * NHEAD + hh) * SEQ * HDIM;
        const __half* Vg = g_v + (bb * NHEAD + hh) * HDIM * SEQ;

        uint32_t qa[4][4];
        {
            int r0 = (q0 + wbase + g) * 32;
            int r1 = r0 + 8 * 32;
            #pragma unroll
            for (int kk = 0; kk < 4; kk++) {
                qa[kk][0] = Qw[r0 + kk * 8 + t];
                qa[kk][1] = Qw[r1 + kk * 8 + t];
                qa[kk][2] = Qw[r0 + kk * 8 + t + 4];
                qa[kk][3] = Qw[r1 + kk * 8 + t + 4];
            }
        }

        float o[8][4] = {};
        float m_run[2] = {-1e30f, -1e30f}, l_run[2] = {0.f, 0.f};

        for (int k0 = 0; k0 < SEQ; k0 += 64) {
            __syncthreads();
            {
                const uint4* K4 = reinterpret_cast<const uint4*>(Kg);
                const uint4* V4 = reinterpret_cast<const uint4*>(Vg);
                #pragma unroll
                for (int e = 0; e < 2; e++) {
                    int idx = tid + e * 256;
                    int r = idx >> 3, c = idx & 7;
                    uint4 kv = K4[(k0 + r) * 8 + c];
                    *reinterpret_cast<uint2*>(Ks + r * 36 + c * 4)     = make_uint2(kv.x, kv.y);
                    *reinterpret_cast<uint2*>(Ks + r * 36 + c * 4 + 2) = make_uint2(kv.z, kv.w);
                    uint4 vv = V4[r * (SEQ / 8) + (k0 >> 3) + c];
                    *reinterpret_cast<uint2*>(Vs + r * 36 + c * 4)     = make_uint2(vv.x, vv.y);
                    *reinterpret_cast<uint2*>(Vs + r * 36 + c * 4 + 2) = make_uint2(vv.z, vv.w);
                }
                if (tid < 64) Ms[tid] = mask[bb * SEQ + k0 + tid];
            }
            __syncthreads();

            float s[8][4] = {};
            #pragma unroll
            for (int kk = 0; kk < 4; kk++) {
                #pragma unroll
                for (int nt = 0; nt < 8; nt++) {
                    const uint32_t* kr = Ks + (nt * 8 + g) * 36 + kk * 8;
                    mma16(s[nt], qa[kk][0], qa[kk][1], qa[kk][2], qa[kk][3],
                          kr[t], kr[t + 4]);
                }
            }

            float2 mk2[8];
            #pragma unroll
            for (int nt = 0; nt < 8; nt++)
                mk2[nt] = *reinterpret_cast<const float2*>(Ms + nt * 8 + 2 * t);

            #pragma unroll
            for (int hs = 0; hs < 2; hs++) {
                float mm = -1e30f;
                #pragma unroll
                for (int nt = 0; nt < 8; nt++) {
                    float v0 = s[nt][hs * 2 + 0] + mk2[nt].x;
                    float v1 = s[nt][hs * 2 + 1] + mk2[nt].y;
                    s[nt][hs * 2 + 0] = v0;
                    s[nt][hs * 2 + 1] = v1;
                    mm = fmaxf(mm, fmaxf(v0, v1));
                }
                mm = fmaxf(mm, __shfl_xor_sync(0xffffffffu, mm, 1));
                mm = fmaxf(mm, __shfl_xor_sync(0xffffffffu, mm, 2));

                float mn = fmaxf(m_run[hs], mm);
                float alpha = __expf(m_run[hs] - mn);
                m_run[hs] = mn;

                float ps = 0.f;
                #pragma unroll
                for (int nt = 0; nt < 8; nt++) {
                    float p0 = __expf(s[nt][hs * 2 + 0] - mn);
                    float p1 = __expf(s[nt][hs * 2 + 1] - mn);
                    s[nt][hs * 2 + 0] = p0;
                    s[nt][hs * 2 + 1] = p1;
                    ps += p0 + p1;
                }
                ps += __shfl_xor_sync(0xffffffffu, ps, 1);
                ps += __shfl_xor_sync(0xffffffffu, ps, 2);
                l_run[hs] = l_run[hs] * alpha + ps;

                #pragma unroll
                for (int nt = 0; nt < 8; nt++) {
                    o[nt][hs * 2 + 0] *= alpha;
                    o[nt][hs * 2 + 1] *= alpha;
                }
            }

            {
                uint32_t* pr0 = Ps + (wbase + g) * 36;
                uint32_t* pr1 = pr0 + 8 * 36;
                #pragma unroll
                for (int nt = 0; nt < 8; nt++) {
                    pr0[nt * 4 + t] = pack2(s[nt][0], s[nt][1]);
                    pr1[nt * 4 + t] = pack2(s[nt][2], s[nt][3]);
                }
            }
            __syncwarp();

            #pragma unroll
            for (int kk = 0; kk < 4; kk++) {
                const uint32_t* p0p = Ps + (wbase + g) * 36 + kk * 8;
                const uint32_t* p1p = p0p + 8 * 36;
                uint32_t a0 = p0p[t],     a1 = p1p[t];
                uint32_t a2 = p0p[t + 4], a3 = p1p[t + 4];
                #pragma unroll
                for (int nt = 0; nt < 8; nt++) {
                    const uint32_t* vr = Vs + (nt * 8 + g) * 36 + kk * 8;
                    mma16(o[nt], a0, a1, a2, a3, vr[t], vr[t + 4]);
                }
            }
        }

        #pragma unroll
        for (int hs = 0; hs < 2; hs++) {
            int r = q0 + wbase + g + hs * 8;
            float inv = 1.f / l_run[hs];
            float* orow = out + (bb * SEQ + r) * DMODEL + hh * HDIM;
            #pragma unroll
            for (int nt = 0; nt < 8; nt++) {
                float2 v;
                v.x = o[nt][hs * 2 + 0] * inv;
                v.y = o[nt][hs * 2 + 1] * inv;
                *reinterpret_cast<float2*>(orow + nt * 8 + 2 * t) = v;
            }
        }
    }
}

// ---------------------------------------------------------------------------
extern "C" void kernel_launch(void* const* d_in, const int* in_sizes, int n_in,
                              void* d_out, int out_size)
{
    const float* v1   = (const float*)d_in[0];
    const float* mask = (const float*)d_in[1];
    const float* Wq   = (const float*)d_in[2];
    const float* bq   = (const float*)d_in[3];
    const float* Wk   = (const float*)d_in[4];
    const float* bk   = (const float*)d_in[5];
    const float* Wv   = (const float*)d_in[6];
    const float* bv   = (const float*)d_in[7];
    float* out = (float*)d_out;

    // 0) split X and W into fp16 hi/lo (W transposed)
    convx_kernel<<<(MROWS * DMODEL / 4) / 256, 256>>>(v1);
    dim3 gw(DMODEL / 32, DMODEL / 32, 3);
    convw_kernel<<<gw, 256>>>(Wq, Wk, Wv);

    // 1) QKV GEMM
    dim3 g1(DMODEL / 64, MROWS / 128, 3);
    qkv_kernel<<<g1, 256>>>(bq, bk, bv);

    // 2) attention: persistent static round-robin
    const int smem_bytes = (64 * 36 + 64 * 36 + 128 * 36) * 4 + 64 * 4;
    cudaFuncSetAttribute(attn_kernel, cudaFuncAttributeMaxDynamicSharedMemorySize,
                         smem_bytes);
    attn_kernel<<<ATTN_GRID, 256, smem_bytes>>>(mask, out);
}

// round 17
// speedup vs baseline: 2.0073x; 1.1926x over previous
#include <cuda_runtime.h>
#include <cuda_fp16.h>
#include <cstdint>

#define BATCH 2
#define SEQ   2048
#define DMODEL 768
#define NHEAD 12
#define HDIM  64
#define MROWS (BATCH*SEQ)            // 4096
#define QTILES (SEQ/128)             // 16
#define NTILES (QTILES*BATCH*NHEAD)  // 384
#define ATTN_GRID 296                // 2 CTAs x 148 SMs
#define LOG2E 1.44269504f

// Pre-split inputs (fp16 hi/lo). Wt is transposed: [z][n][k].
__device__ __half g_xh[MROWS*DMODEL], g_xl[MROWS*DMODEL];
__device__ __half g_wh[3*DMODEL*DMODEL], g_wl[3*DMODEL*DMODEL];
// Scratch fp16: Q [B,H,S,hd] pre-scaled 0.125*log2(e), K [B,H,S,hd], V [B,H,hd,S]
__device__ __half g_q[BATCH*NHEAD*SEQ*HDIM];
__device__ __half g_k[BATCH*NHEAD*SEQ*HDIM];
__device__ __half g_v[BATCH*NHEAD*SEQ*HDIM];

// ---------------------------------------------------------------------------
// helpers
// ---------------------------------------------------------------------------
__device__ __forceinline__ uint32_t pack2(float a, float b) {
    __half2 h = __floats2half2_rn(a, b);
    return *reinterpret_cast<uint32_t*>(&h);
}
__device__ __forceinline__ void splith(float v, __half& h, __half& l) {
    h = __float2half_rn(v);
    l = __float2half_rn(v - __half2float(h));
}
__device__ __forceinline__ float ex2(float x) {
    float r; asm("ex2.approx.f32 %0, %1;" : "=f"(r) : "f"(x)); return r;
}
// D += A(m16k16,row) * B(k16n8,col), fp16 inputs, fp32 accum
__device__ __forceinline__ void mma16(float* c,
    uint32_t a0, uint32_t a1, uint32_t a2, uint32_t a3,
    uint32_t b0, uint32_t b1)
{
    asm volatile(
        "mma.sync.aligned.m16n8k16.row.col.f32.f16.f16.f32 "
        "{%0,%1,%2,%3}, {%4,%5,%6,%7}, {%8,%9}, {%0,%1,%2,%3};"
        : "+f"(c[0]), "+f"(c[1]), "+f"(c[2]), "+f"(c[3])
        : "r"(a0), "r"(a1), "r"(a2), "r"(a3), "r"(b0), "r"(b1));
}
__device__ __forceinline__ void ldsm4(uint32_t& r0, uint32_t& r1,
                                      uint32_t& r2, uint32_t& r3, uint32_t addr)
{
    asm volatile("ldmatrix.sync.aligned.m8n8.x4.shared.b16 {%0,%1,%2,%3}, [%4];"
        : "=r"(r0), "=r"(r1), "=r"(r2), "=r"(r3) : "r"(addr));
}

// ---------------------------------------------------------------------------
// Kernel 0a: split X into fp16 hi/lo
// ---------------------------------------------------------------------------
__global__ __launch_bounds__(256) void convx_kernel(const float* __restrict__ X)
{
    int i = blockIdx.x * 256 + threadIdx.x;     // float4 index
    float4 v = reinterpret_cast<const float4*>(X)[i];
    __half h0, l0, h1, l1, h2, l2, h3, l3;
    splith(v.x, h0, l0); splith(v.y, h1, l1);
    splith(v.z, h2, l2); splith(v.w, h3, l3);
    __half2 H0 = __halves2half2(h0, h1), H1 = __halves2half2(h2, h3);
    __half2 L0 = __halves2half2(l0, l1), L1 = __halves2half2(l2, l3);
    reinterpret_cast<uint2*>(g_xh)[i] = make_uint2(*(uint32_t*)&H0, *(uint32_t*)&H1);
    reinterpret_cast<uint2*>(g_xl)[i] = make_uint2(*(uint32_t*)&L0, *(uint32_t*)&L1);
}

// ---------------------------------------------------------------------------
// Kernel 0b: transpose + split W -> Wt[z][n][k] fp16 hi/lo. 32x32 tiles.
// ---------------------------------------------------------------------------
__global__ __launch_bounds__(256) void convw_kernel(
    const float* __restrict__ Wq, const float* __restrict__ Wk,
    const float* __restrict__ Wv)
{
    const int z = blockIdx.z;
    const float* __restrict__ W = (z == 0) ? Wq : (z == 1) ? Wk : Wv;
    __shared__ float tile[32][33];
    const int k0 = blockIdx.x * 32, n0 = blockIdx.y * 32;
    const int tx = threadIdx.x & 31, ty = threadIdx.x >> 5;   // 32 x 8
    #pragma unroll
    for (int j = 0; j < 4; j++)
        tile[ty * 4 + j][tx] = W[(k0 + ty * 4 + j) * DMODEL + n0 + tx];
    __syncthreads();
    #pragma unroll
    for (int j = 0; j < 4; j++) {
        int n = n0 + ty * 4 + j;
        float v = tile[tx][ty * 4 + j];
        __half h, l; splith(v, h, l);
        g_wh[z * DMODEL * DMODEL + n * DMODEL + k0 + tx] = h;
        g_wl[z * DMODEL * DMODEL + n * DMODEL + k0 + tx] = l;
    }
}

// ---------------------------------------------------------------------------
// Kernel 1: QKV GEMM, 2xFP16 split (hh+hl+lh). 256 thr, BM=128, BN=64, BK=32.
// COALESCED loads: 4 lanes per row (64B contiguous). smem stride 20 u32.
// Outputs fp16: Q scaled 0.125*log2e; V transposed [B,H,hd,S].
// ---------------------------------------------------------------------------
__global__ __launch_bounds__(256, 2) void qkv_kernel(
    const float* __restrict__ bq, const float* __restrict__ bk,
    const float* __restrict__ bv)
{
    const int z = blockIdx.z;
    const float* __restrict__ bias = (z == 0) ? bq : (z == 1) ? bk : bv;
    __half* __restrict__ out       = (z == 0) ? g_q : (z == 1) ? g_k : g_v;
    const float osc = (z == 0) ? 0.125f * LOG2E : 1.0f;

    __shared__ uint32_t Ah[128 * 20], Al[128 * 20];   // [m][kpair(16)] pad 20
    __shared__ uint32_t Bh[64 * 20],  Bl[64 * 20];    // [n][kpair(16)] pad 20

    const int tid  = threadIdx.x;
    const int warp = tid >> 5;
    const int lane = tid & 31;
    const int g = lane >> 2;
    const int t = lane & 3;
    const int wy = warp >> 1;         // 0..3
    const int wx = warp & 1;          // 0..1

    const int m0 = blockIdx.y * 128;
    const int n0 = blockIdx.x * 64;

    const uint4* Xh4 = reinterpret_cast<const uint4*>(g_xh);
    const uint4* Xl4 = reinterpret_cast<const uint4*>(g_xl);
    const uint4* Wh4 = reinterpret_cast<const uint4*>(g_wh + z * DMODEL * DMODEL);
    const uint4* Wl4 = reinterpret_cast<const uint4*>(g_wl + z * DMODEL * DMODEL);

    // A: 512 uint4/array, 2/thread: r = idx>>2 (row), c = idx&3 (64B contiguous)
    // B: 256 uint4/array, 1/thread: nB = tid>>2, cB = tid&3
    const int rA0 = tid >> 2,            cA0 = tid & 3;       // e=0 rows 0..63
    const int rA1 = 64 + (tid >> 2),     cA1 = tid & 3;       // e=1 rows 64..127
    const int nB = tid >> 2, cB = tid & 3;

    float acc[2][4][4] = {};
    uint4 pah[2], pal[2], pbh, pbl;

    // prefetch first tile
    pah[0] = Xh4[(m0 + rA0) * 96 + cA0]; pal[0] = Xl4[(m0 + rA0) * 96 + cA0];
    pah[1] = Xh4[(m0 + rA1) * 96 + cA1]; pal[1] = Xl4[(m0 + rA1) * 96 + cA1];
    pbh = Wh4[(n0 + nB) * 96 + cB];      pbl = Wl4[(n0 + nB) * 96 + cB];

    for (int k0 = 0; k0 < DMODEL; k0 += 32) {
        __syncthreads();   // previous mma phase done reading smem
        *reinterpret_cast<uint4*>(Ah + rA0 * 20 + cA0 * 4) = pah[0];
        *reinterpret_cast<uint4*>(Al + rA0 * 20 + cA0 * 4) = pal[0];
        *reinterpret_cast<uint4*>(Ah + rA1 * 20 + cA1 * 4) = pah[1];
        *reinterpret_cast<uint4*>(Al + rA1 * 20 + cA1 * 4) = pal[1];
        *reinterpret_cast<uint4*>(Bh + nB * 20 + cB * 4) = pbh;
        *reinterpret_cast<uint4*>(Bl + nB * 20 + cB * 4) = pbl;
        __syncthreads();

        // prefetch next tile (overlaps mma phase)
        if (k0 + 32 < DMODEL) {
            int kb = (k0 + 32) >> 3;
            pah[0] = Xh4[(m0 + rA0) * 96 + kb + cA0];
            pal[0] = Xl4[(m0 + rA0) * 96 + kb + cA0];
            pah[1] = Xh4[(m0 + rA1) * 96 + kb + cA1];
            pal[1] = Xl4[(m0 + rA1) * 96 + kb + cA1];
            pbh = Wh4[(n0 + nB) * 96 + kb + cB];
            pbl = Wl4[(n0 + nB) * 96 + kb + cB];
        }

        #pragma unroll
        for (int kk = 0; kk < 2; kk++) {
            uint32_t ah[2][4], al[2][4];
            #pragma unroll
            for (int mt = 0; mt < 2; mt++) {
                int r0 = (wy * 32 + mt * 16 + g) * 20 + kk * 8;
                int r1 = r0 + 8 * 20;
                ah[mt][0] = Ah[r0 + t];     ah[mt][1] = Ah[r1 + t];
                ah[mt][2] = Ah[r0 + t + 4]; ah[mt][3] = Ah[r1 + t + 4];
                al[mt][0] = Al[r0 + t];     al[mt][1] = Al[r1 + t];
                al[mt][2] = Al[r0 + t + 4]; al[mt][3] = Al[r1 + t + 4];
            }
            #pragma unroll
            for (int nt = 0; nt < 4; nt++) {
                int nr = (wx * 32 + nt * 8 + g) * 20 + kk * 8;
                uint32_t bh0 = Bh[nr + t], bh1 = Bh[nr + t + 4];
                uint32_t bl0 = Bl[nr + t], bl1 = Bl[nr + t + 4];
                #pragma unroll
                for (int mt = 0; mt < 2; mt++) {
                    mma16(acc[mt][nt], ah[mt][0], ah[mt][1], ah[mt][2], ah[mt][3], bh0, bh1);
                    mma16(acc[mt][nt], ah[mt][0], ah[mt][1], ah[mt][2], ah[mt][3], bl0, bl1);
                    mma16(acc[mt][nt], al[mt][0], al[mt][1], al[mt][2], al[mt][3], bh0, bh1);
                }
            }
        }
    }

    // Epilogue: +bias, scale, fp16. Q/K -> [B,H,S,hd]; V -> [B,H,hd,S].
    const int h = n0 >> 6;
    #pragma unroll
    for (int mt = 0; mt < 2; mt++) {
        #pragma unroll
        for (int hs = 0; hs < 2; hs++) {
            int mg = m0 + wy * 32 + mt * 16 + g + hs * 8;
            int bb = mg >> 11;
            int s  = mg & (SEQ - 1);
            #pragma unroll
            for (int nt = 0; nt < 4; nt++) {
                int d = wx * 32 + nt * 8 + 2 * t;
                float v0 = (acc[mt][nt][hs * 2 + 0] + bias[n0 + d])     * osc;
                float v1 = (acc[mt][nt][hs * 2 + 1] + bias[n0 + d + 1]) * osc;
                if (z == 2) {
                    __half* vb = out + (bb * NHEAD + h) * HDIM * SEQ;
                    vb[(d)     * SEQ + s] = __float2half_rn(v0);
                    vb[(d + 1) * SEQ + s] = __float2half_rn(v1);
                } else {
                    uint32_t* orow = reinterpret_cast<uint32_t*>(
                        out + ((bb * NHEAD + h) * SEQ + s) * HDIM);
                    orow[d >> 1] = pack2(v0, v1);
                }
            }
        }
    }
}

// ---------------------------------------------------------------------------
// Kernel 2: flash attention, fp16 m16n8k16, persistent static round-robin.
// Q frags in registers; K/V B-frags via ldmatrix.x4; P never touches smem
// (S C-fragment == PV A-fragment layout). exp2-domain softmax.
// ---------------------------------------------------------------------------
__global__ __launch_bounds__(256, 2) void attn_kernel(
    const float* __restrict__ mask, float* __restrict__ out)
{
    extern __shared__ uint32_t sm4[];
    uint32_t* Ks = sm4;                 // [64][36] u32: [key][dpair]
    uint32_t* Vs = Ks + 64 * 36;        // [64][36] u32: [d][keypair]
    float*    Ms = (float*)(Vs + 64 * 36);        // [64] mask*log2e

    const int tid  = threadIdx.x;
    const int warp = tid >> 5;
    const int lane = tid & 31;
    const int g = lane >> 2;
    const int t = lane & 3;
    const int wbase = warp * 16;

    const uint32_t ks0 = (uint32_t)__cvta_generic_to_shared(Ks);
    const uint32_t vs0 = (uint32_t)__cvta_generic_to_shared(Vs);
    // ldmatrix.x4 lane->row/col mapping (4 matrices: b0/b1 for nt, nt+1)
    const int lrow = (lane & 7) + ((lane >> 4) << 3);
    const int lcol = ((lane >> 3) & 1) << 2;

    for (int tile = blockIdx.x; tile < NTILES; tile += ATTN_GRID) {
        const int pair = tile >> 4;
        const int qt   = tile & (QTILES - 1);
        const int bb = pair / NHEAD;
        const int hh = pair % NHEAD;
        const int q0 = qt * 128;

        const uint32_t* Qw = reinterpret_cast<const uint32_t*>(g_q)
                           + (bb * NHEAD + hh) * SEQ * (HDIM / 2);
        const __half* Kg = g_k + (bb * NHEAD + hh) * SEQ * HDIM;
        const __half* Vg = g_v + (bb * NHEAD + hh) * HDIM * SEQ;

        // Q fragments -> registers (reused across all key tiles)
        uint32_t qa[4][4];
        {
            int r0 = (q0 + wbase + g) * 32;
            int r1 = r0 + 8 * 32;
            #pragma unroll
            for (int kk = 0; kk < 4; kk++) {
                qa[kk][0] = Qw[r0 + kk * 8 + t];
                qa[kk][1] = Qw[r1 + kk * 8 + t];
                qa[kk][2] = Qw[r0 + kk * 8 + t + 4];
                qa[kk][3] = Qw[r1 + kk * 8 + t + 4];
            }
        }

        float o[8][4] = {};
        float m_run[2] = {-1e30f, -1e30f}, l_run[2] = {0.f, 0.f};

        for (int k0 = 0; k0 < SEQ; k0 += 64) {
            __syncthreads();   // prev iter done reading Ks/Vs
            {
                const uint4* K4 = reinterpret_cast<const uint4*>(Kg);
                const uint4* V4 = reinterpret_cast<const uint4*>(Vg);
                #pragma unroll
                for (int e = 0; e < 2; e++) {
                    int idx = tid + e * 256;
                    int r = idx >> 3, c = idx & 7;
                    *reinterpret_cast<uint4*>(Ks + r * 36 + c * 4) =
                        K4[(k0 + r) * 8 + c];
                    *reinterpret_cast<uint4*>(Vs + r * 36 + c * 4) =
                        V4[r * (SEQ / 8) + (k0 >> 3) + c];
                }
                if (tid < 64) Ms[tid] = mask[bb * SEQ + k0 + tid] * LOG2E;
            }
            __syncthreads();

            // ---- S = Q K^T : warp m16 x n64 (B frags via ldmatrix.x4) ----
            float s[8][4] = {};
            #pragma unroll
            for (int kk = 0; kk < 4; kk++) {
                #pragma unroll
                for (int ntp = 0; ntp < 4; ntp++) {
                    uint32_t b0, b1, b2, b3;
                    uint32_t addr = ks0 +
                        (((ntp * 16 + lrow) * 36) + kk * 8 + lcol) * 4;
                    ldsm4(b0, b1, b2, b3, addr);
                    mma16(s[2 * ntp],     qa[kk][0], qa[kk][1], qa[kk][2], qa[kk][3], b0, b1);
                    mma16(s[2 * ntp + 1], qa[kk][0], qa[kk][1], qa[kk][2], qa[kk][3], b2, b3);
                }
            }

            // ---- online softmax (exp2 domain; rows wbase+g, wbase+g+8) ----
            float2 mk2[8];
            #pragma unroll
            for (int nt = 0; nt < 8; nt++)
                mk2[nt] = *reinterpret_cast<const float2*>(Ms + nt * 8 + 2 * t);

            #pragma unroll
            for (int hs = 0; hs < 2; hs++) {
                float mm = -1e30f;
                #pragma unroll
                for (int nt = 0; nt < 8; nt++) {
                    float v0 = s[nt][hs * 2 + 0] + mk2[nt].x;
                    float v1 = s[nt][hs * 2 + 1] + mk2[nt].y;
                    s[nt][hs * 2 + 0] = v0;
                    s[nt][hs * 2 + 1] = v1;
                    mm = fmaxf(mm, fmaxf(v0, v1));
                }
                mm = fmaxf(mm, __shfl_xor_sync(0xffffffffu, mm, 1));
                mm = fmaxf(mm, __shfl_xor_sync(0xffffffffu, mm, 2));

                float mn = fmaxf(m_run[hs], mm);
                float alpha = ex2(m_run[hs] - mn);
                m_run[hs] = mn;

                float ps = 0.f;
                #pragma unroll
                for (int nt = 0; nt < 8; nt++) {
                    float p0 = ex2(s[nt][hs * 2 + 0] - mn);
                    float p1 = ex2(s[nt][hs * 2 + 1] - mn);
                    s[nt][hs * 2 + 0] = p0;
                    s[nt][hs * 2 + 1] = p1;
                    ps += p0 + p1;
                }
                ps += __shfl_xor_sync(0xffffffffu, ps, 1);
                ps += __shfl_xor_sync(0xffffffffu, ps, 2);
                l_run[hs] = l_run[hs] * alpha + ps;

                #pragma unroll
                for (int nt = 0; nt < 8; nt++) {
                    o[nt][hs * 2 + 0] *= alpha;
                    o[nt][hs * 2 + 1] *= alpha;
                }
            }

            // ---- O += P V : P taken straight from the S fragment ----
            #pragma unroll
            for (int kk = 0; kk < 4; kk++) {
                uint32_t a0 = pack2(s[2 * kk][0],     s[2 * kk][1]);
                uint32_t a1 = pack2(s[2 * kk][2],     s[2 * kk][3]);
                uint32_t a2 = pack2(s[2 * kk + 1][0], s[2 * kk + 1][1]);
                uint32_t a3 = pack2(s[2 * kk + 1][2], s[2 * kk + 1][3]);
                #pragma unroll
                for (int ntp = 0; ntp < 4; ntp++) {
                    uint32_t b0, b1, b2, b3;
                    uint32_t addr = vs0 +
                        (((ntp * 16 + lrow) * 36) + kk * 8 + lcol) * 4;
                    ldsm4(b0, b1, b2, b3, addr);
                    mma16(o[2 * ntp],     a0, a1, a2, a3, b0, b1);
                    mma16(o[2 * ntp + 1], a0, a1, a2, a3, b2, b3);
                }
            }
        }

        // ---- normalize + write out [B,S,D] ----
        #pragma unroll
        for (int hs = 0; hs < 2; hs++) {
            int r = q0 + wbase + g + hs * 8;
            float inv = 1.f / l_run[hs];
            float* orow = out + (bb * SEQ + r) * DMODEL + hh * HDIM;
            #pragma unroll
            for (int nt = 0; nt < 8; nt++) {
                float2 v;
                v.x = o[nt][hs * 2 + 0] * inv;
                v.y = o[nt][hs * 2 + 1] * inv;
                *reinterpret_cast<float2*>(orow + nt * 8 + 2 * t) = v;
            }
        }
    }
}

// ---------------------------------------------------------------------------
extern "C" void kernel_launch(void* const* d_in, const int* in_sizes, int n_in,
                              void* d_out, int out_size)
{
    const float* v1   = (const float*)d_in[0];
    const float* mask = (const float*)d_in[1];
    const float* Wq   = (const float*)d_in[2];
    const float* bq   = (const float*)d_in[3];
    const float* Wk   = (const float*)d_in[4];
    const float* bk   = (const float*)d_in[5];
    const float* Wv   = (const float*)d_in[6];
    const float* bv   = (const float*)d_in[7];
    float* out = (float*)d_out;

    // 0) split X and W into fp16 hi/lo (W transposed)
    convx_kernel<<<(MROWS * DMODEL / 4) / 256, 256>>>(v1);
    dim3 gw(DMODEL / 32, DMODEL / 32, 3);
    convw_kernel<<<gw, 256>>>(Wq, Wk, Wv);

    // 1) QKV GEMM
    dim3 g1(DMODEL / 64, MROWS / 128, 3);
    qkv_kernel<<<g1, 256>>>(bq, bk, bv);

    // 2) attention: persistent static round-robin.  smem 18.7 KB
    const int smem_bytes = (64 * 36 + 64 * 36) * 4 + 64 * 4;
    cudaFuncSetAttribute(attn_kernel, cudaFuncAttributeMaxDynamicSharedMemorySize,
                         smem_bytes);
    attn_kernel<<<ATTN_GRID, 256, smem_bytes>>>(mask, out);
}